// round 8
// baseline (speedup 1.0000x reference)
#include <cuda_runtime.h>
#include <cuda_fp16.h>
#include <cuda_bf16.h>
#include <math.h>

// ---------------- problem constants ----------------
#define BB    16
#define NN    1024
#define DD    64
#define EPSF  0.1f
#define MAXIT 100
#define THRF  0.1f
#define GRD   128
#define TPB   512

// ---------------- packed f32x2 helpers ----------------
typedef unsigned long long ull;
__device__ __forceinline__ ull pk2(float lo, float hi) {
    ull r; asm("mov.b64 %0, {%1, %2};" : "=l"(r) : "f"(lo), "f"(hi)); return r;
}
__device__ __forceinline__ void up2(ull v, float& lo, float& hi) {
    asm("mov.b64 {%0, %1}, %2;" : "=f"(lo), "=f"(hi) : "l"(v));
}
#define FMA2(d, a, b) asm("fma.rn.f32x2 %0, %1, %2, %0;" : "+l"(d) : "l"(a), "l"(b))

// butterfly-shuffle reductions
__device__ __forceinline__ float warp_sum(float v) {
    #pragma unroll
    for (int o = 16; o; o >>= 1) v += __shfl_xor_sync(0xffffffffu, v, o);
    return v;
}
__device__ __forceinline__ float seg8_sum(float v) {
    v += __shfl_xor_sync(0xffffffffu, v, 1);
    v += __shfl_xor_sync(0xffffffffu, v, 2);
    v += __shfl_xor_sync(0xffffffffu, v, 4);
    return v;
}

// ---------------- mma / ldmatrix helpers ----------------
__device__ __forceinline__ void ldsm4(unsigned& r0, unsigned& r1, unsigned& r2,
                                      unsigned& r3, unsigned addr) {
    asm volatile("ldmatrix.sync.aligned.m8n8.x4.shared.b16 {%0,%1,%2,%3}, [%4];"
                 : "=r"(r0), "=r"(r1), "=r"(r2), "=r"(r3) : "r"(addr));
}
__device__ __forceinline__ void ldsm4t(unsigned& r0, unsigned& r1, unsigned& r2,
                                       unsigned& r3, unsigned addr) {
    asm volatile("ldmatrix.sync.aligned.m8n8.x4.trans.shared.b16 {%0,%1,%2,%3}, [%4];"
                 : "=r"(r0), "=r"(r1), "=r"(r2), "=r"(r3) : "r"(addr));
}
__device__ __forceinline__ void ldsm2t(unsigned& r0, unsigned& r1, unsigned addr) {
    asm volatile("ldmatrix.sync.aligned.m8n8.x2.trans.shared.b16 {%0,%1}, [%2];"
                 : "=r"(r0), "=r"(r1) : "r"(addr));
}
__device__ __forceinline__ void mma16816(float* d, const unsigned* a,
                                         unsigned b0, unsigned b1) {
    asm volatile(
        "mma.sync.aligned.m16n8k16.row.col.f32.bf16.bf16.f32 "
        "{%0,%1,%2,%3}, {%4,%5,%6,%7}, {%8,%9}, {%0,%1,%2,%3};"
        : "+f"(d[0]), "+f"(d[1]), "+f"(d[2]), "+f"(d[3])
        : "r"(a[0]), "r"(a[1]), "r"(a[2]), "r"(a[3]), "r"(b0), "r"(b1));
}
__device__ __forceinline__ void mma16816h(float* d, const unsigned* a,
                                          unsigned b0, unsigned b1) {
    asm volatile(
        "mma.sync.aligned.m16n8k16.row.col.f32.f16.f16.f32 "
        "{%0,%1,%2,%3}, {%4,%5,%6,%7}, {%8,%9}, {%0,%1,%2,%3};"
        : "+f"(d[0]), "+f"(d[1]), "+f"(d[2]), "+f"(d[3])
        : "r"(a[0]), "r"(a[1]), "r"(a[2]), "r"(a[3]), "r"(b0), "r"(b1));
}

// ---------------- device scratch ----------------
__device__ __nv_bfloat16 g_xh[BB * NN * DD];
__device__ __nv_bfloat16 g_xl[BB * NN * DD];
__device__ __nv_bfloat16 g_yh[BB * NN * DD];
__device__ __nv_bfloat16 g_yl[BB * NN * DD];
__device__ __align__(16) __half g_yf[BB * NN * DD];         // y fp16 for W-pass
__device__ float g_x2[BB * NN];
__device__ float g_y2[BB * NN];
__device__ __align__(16) __half g_Kh[(size_t)BB * NN * NN]; // 32 MB fp16 kernel
__device__ float g_colPart[2][GRD * NN];
__device__ float g_errPart[2][GRD];
__device__ double g_cost;
__device__ unsigned g_bar;

// ---------------- softmax: 8 threads per (x-row, y-row) pair ----------------
__global__ void __launch_bounds__(256) softmax_kernel(const float* __restrict__ x,
                                                      const float* __restrict__ y) {
    if (blockIdx.x == 0 && threadIdx.x == 0) { g_cost = 0.0; g_bar = 0u; }
    int t   = blockIdx.x * blockDim.x + threadIdx.x;
    int row = t >> 3;                  // 0..BB*NN-1, handles x-row AND y-row
    int lg  = t & 7;

    const float4* rx = (const float4*)(x + (size_t)row * DD);
    const float4* ry = (const float4*)(y + (size_t)row * DD);
    float4 a0 = rx[lg * 2], a1 = rx[lg * 2 + 1];
    float4 b0 = ry[lg * 2], b1 = ry[lg * 2 + 1];

    float ex[8] = {__expf(a0.x), __expf(a0.y), __expf(a0.z), __expf(a0.w),
                   __expf(a1.x), __expf(a1.y), __expf(a1.z), __expf(a1.w)};
    float ey[8] = {__expf(b0.x), __expf(b0.y), __expf(b0.z), __expf(b0.w),
                   __expf(b1.x), __expf(b1.y), __expf(b1.z), __expf(b1.w)};
    float sx = ((ex[0]+ex[1])+(ex[2]+ex[3])) + ((ex[4]+ex[5])+(ex[6]+ex[7]));
    float sy = ((ey[0]+ey[1])+(ey[2]+ey[3])) + ((ey[4]+ey[5])+(ey[6]+ey[7]));
    sx = seg8_sum(sx); sy = seg8_sum(sy);
    float ix = 1.0f / sx, iy = 1.0f / sy;

    float px[8], py[8], qx = 0.0f, qy = 0.0f;
    #pragma unroll
    for (int k = 0; k < 8; k++) {
        px[k] = ex[k] * ix; qx += px[k] * px[k];
        py[k] = ey[k] * iy; qy += py[k] * py[k];
    }

    union { __nv_bfloat162 h2[4]; uint4 u; } xhh, xll, yhh, yll;
    union { __half2 h2[4]; uint4 u; } yff;
    #pragma unroll
    for (int k = 0; k < 4; k++) {
        __nv_bfloat16 h0 = __float2bfloat16_rn(px[2*k]);
        __nv_bfloat16 h1 = __float2bfloat16_rn(px[2*k+1]);
        xhh.h2[k].x = h0; xhh.h2[k].y = h1;
        xll.h2[k].x = __float2bfloat16_rn(px[2*k]   - __bfloat162float(h0));
        xll.h2[k].y = __float2bfloat16_rn(px[2*k+1] - __bfloat162float(h1));
        __nv_bfloat16 g0 = __float2bfloat16_rn(py[2*k]);
        __nv_bfloat16 g1 = __float2bfloat16_rn(py[2*k+1]);
        yhh.h2[k].x = g0; yhh.h2[k].y = g1;
        yll.h2[k].x = __float2bfloat16_rn(py[2*k]   - __bfloat162float(g0));
        yll.h2[k].y = __float2bfloat16_rn(py[2*k+1] - __bfloat162float(g1));
        yff.h2[k] = __floats2half2_rn(py[2*k], py[2*k+1]);
    }
    size_t base = (size_t)row * DD + lg * 8;
    *(uint4*)(g_xh + base) = xhh.u;
    *(uint4*)(g_xl + base) = xll.u;
    *(uint4*)(g_yh + base) = yhh.u;
    *(uint4*)(g_yl + base) = yll.u;
    *(uint4*)(g_yf + base) = yff.u;

    qx = seg8_sum(qx); qy = seg8_sum(qy);
    if (lg == 0) { g_x2[row] = qx; g_y2[row] = qy; }
}

// ---------------- tensor GEMM: K = exp(-(x2+y2-2XY^T)/eps) only -------------
#define ROWP 72
#define TILEH (128 * ROWP)
#define EPIST 136
__global__ void __launch_bounds__(256) gemm_kernel() {
    extern __shared__ __half sm[];
    const int b  = blockIdx.z;
    const int i0 = blockIdx.y * 128;
    const int j0 = blockIdx.x * 128;
    const int t  = threadIdx.x;
    const int wid  = t >> 5;
    const int lane = t & 31;
    const int wm = wid & 3;
    const int wn = wid >> 2;

    {
        const __nv_bfloat16* srcs[4] = {
            g_xh + ((size_t)b * NN + i0) * DD, g_xl + ((size_t)b * NN + i0) * DD,
            g_yh + ((size_t)b * NN + j0) * DD, g_yl + ((size_t)b * NN + j0) * DD };
        #pragma unroll
        for (int ts = 0; ts < 4; ts++) {
            const uint4* s = (const uint4*)srcs[ts];
            #pragma unroll
            for (int q = 0; q < 4; q++) {
                int idx = t + q * 256;
                int row = idx >> 3, seg = idx & 7;
                uint4 v = s[idx];
                *(uint4*)(sm + ts * TILEH + row * ROWP + seg * 8) = v;
            }
        }
    }
    __syncthreads();

    float acc[2][8][4];
    #pragma unroll
    for (int mt = 0; mt < 2; mt++)
        #pragma unroll
        for (int nt = 0; nt < 8; nt++)
            #pragma unroll
            for (int e = 0; e < 4; e++) acc[mt][nt][e] = 0.0f;

    const unsigned smBase = (unsigned)__cvta_generic_to_shared(sm);
    const int aRowOff = (lane & 7) + (lane & 8);
    const int aColOff = (lane & 16) >> 1;
    const int bRowOff = (lane & 7) + ((lane & 16) >> 1);
    const int bColOff = (lane & 8);

    #pragma unroll
    for (int pass = 0; pass < 3; pass++) {
        const int asel = (pass == 2) ? 1 : 0;
        const int bsel = (pass == 1) ? 1 : 0;
        const unsigned aBase = smBase + asel * TILEH * 2;
        const unsigned bBase = smBase + (2 + bsel) * TILEH * 2;
        #pragma unroll
        for (int ks = 0; ks < 4; ks++) {
            const int kcol = ks * 16;
            unsigned afr[2][4];
            #pragma unroll
            for (int mt = 0; mt < 2; mt++) {
                unsigned addr = aBase +
                    ((wm * 32 + mt * 16 + aRowOff) * ROWP + kcol + aColOff) * 2;
                ldsm4(afr[mt][0], afr[mt][1], afr[mt][2], afr[mt][3], addr);
            }
            unsigned bfr[4][4];
            #pragma unroll
            for (int nq = 0; nq < 4; nq++) {
                unsigned addr = bBase +
                    ((wn * 64 + nq * 16 + bRowOff) * ROWP + kcol + bColOff) * 2;
                ldsm4(bfr[nq][0], bfr[nq][1], bfr[nq][2], bfr[nq][3], addr);
            }
            #pragma unroll
            for (int mt = 0; mt < 2; mt++)
                #pragma unroll
                for (int nq = 0; nq < 4; nq++) {
                    mma16816(acc[mt][2 * nq],     afr[mt], bfr[nq][0], bfr[nq][1]);
                    mma16816(acc[mt][2 * nq + 1], afr[mt], bfr[nq][2], bfr[nq][3]);
                }
        }
    }

    // ---- epilogue: K only, staged through smem, coalesced stores ----
    const int g  = lane >> 2;
    const int t4 = lane & 3;
    float y2v[16];
    #pragma unroll
    for (int nt = 0; nt < 8; nt++) {
        int gj = j0 + wn * 64 + nt * 8 + t4 * 2;
        y2v[2 * nt]     = g_y2[b * NN + gj];
        y2v[2 * nt + 1] = g_y2[b * NN + gj + 1];
    }
    __syncthreads();
    __half* smK = sm;
    #pragma unroll
    for (int mt = 0; mt < 2; mt++) {
        #pragma unroll
        for (int hh = 0; hh < 2; hh++) {
            int lrow = wm * 32 + mt * 16 + hh * 8 + g;
            float x2i = g_x2[b * NN + i0 + lrow];
            #pragma unroll
            for (int nt = 0; nt < 8; nt++) {
                int lcol = wn * 64 + nt * 8 + t4 * 2;
                float d0 = acc[mt][nt][hh * 2 + 0];
                float d1 = acc[mt][nt][hh * 2 + 1];
                float c0 = x2i + y2v[2 * nt]     - 2.0f * d0;
                float c1 = x2i + y2v[2 * nt + 1] - 2.0f * d1;
                *(__half2*)(smK + lrow * EPIST + lcol) =
                    __floats2half2_rn(__expf(-10.0f * c0), __expf(-10.0f * c1));
            }
        }
    }
    __syncthreads();
    #pragma unroll
    for (int q = 0; q < 8; q++) {
        int idx = q * 256 + t;
        int row = idx >> 4, seg = idx & 15;
        uint4 v = *(const uint4*)(smK + row * EPIST + seg * 8);
        *(uint4*)(g_Kh + ((size_t)b * NN + i0 + row) * NN + j0 + seg * 8) = v;
    }
}

// ---------------- software grid barrier (tight spin) ----------------
__device__ __forceinline__ void grid_barrier(unsigned& target) {
    target += GRD;
    __syncthreads();
    if (threadIdx.x == 0) {
        __threadfence();
        atomicAdd(&g_bar, 1u);
        volatile unsigned* p = &g_bar;
        while (*p < target) { }
        __threadfence();
    }
    __syncthreads();
}

// ---------------- persistent Sinkhorn + tensor-core cost pass ----------------
#define COLSTRIDE 1026
#define SH_FLOATS (1024 + 1024 + 128 + 16 * COLSTRIDE + 32)

__global__ void __launch_bounds__(TPB) sinkhorn_kernel(float* __restrict__ out) {
    extern __shared__ float sh[];
    float* shB   = sh;                  // exp(v/eps)
    float* shV   = sh + 1024;           // v (reused as b-fp16 in final phase)
    float* shU   = sh + 2048;           // u (owned 128 rows)
    float* shCol = sh + 2176;           // reused as P/Y/W in final phase
    float* shRed = shCol + 16 * COLSTRIDE;

    const int tid  = threadIdx.x;
    const int w    = tid >> 5;
    const int lane = tid & 31;
    const int bid  = blockIdx.x;
    const int tb   = bid >> 3;
    unsigned target = 0;
    const float log_mu  = logf(1.0f / NN + 1e-8f);
    const float inv_eps = 1.0f / EPSF;
    bool stop = false;

    for (int i = tid; i < 1024; i += TPB) { shB[i] = 1.0f; shV[i] = 0.0f; }
    if (tid < 128) shU[tid] = 0.0f;
    __syncthreads();

    for (int it = 0; it < MAXIT && !stop; ++it) {
        const int pb = it & 1;
        ull colAcc[16];
        #pragma unroll
        for (int q = 0; q < 16; q++) colAcc[q] = 0ULL;
        float errAcc = 0.0f;
        const int rowLocalBase = w * 8;

        #pragma unroll 2
        for (int r = 0; r < 8; r++) {
            const int rl  = rowLocalBase + r;
            const int row = bid * 128 + rl;
            const uint4* __restrict__ Kr = (const uint4*)(g_Kh + (size_t)row * NN);
            ull kf[16];
            ull s2 = 0ULL;
            #pragma unroll
            for (int tt = 0; tt < 4; tt++) {
                uint4 q4 = Kr[lane + 32 * tt];
                const __half2* hp = (const __half2*)&q4;
                const ull* bp = (const ull*)(shB + ((lane + 32 * tt) << 3));
                #pragma unroll
                for (int e = 0; e < 4; e++) {
                    float2 f = __half22float2(hp[e]);
                    kf[tt * 4 + e] = pk2(f.x, f.y);
                    FMA2(s2, kf[tt * 4 + e], bp[e]);
                }
            }
            float sx, sy; up2(s2, sx, sy);
            float s = warp_sum(sx + sy);

            float uo  = shU[rl];
            float ao  = __expf(uo * inv_eps);
            float lse = __logf(fmaf(ao, s, 1e-6f));
            float un  = EPSF * (log_mu - lse) + uo;
            float an  = __expf(un * inv_eps);
            if (lane == 0) { shU[rl] = un; errAcc += fabsf(un - uo); }
            ull ap = pk2(an, an);
            #pragma unroll
            for (int q = 0; q < 16; q++) FMA2(colAcc[q], ap, kf[q]);
        }

        if (lane == 0) shRed[w] = errAcc;
        {
            float* dst = shCol + w * COLSTRIDE;
            #pragma unroll
            for (int tt = 0; tt < 4; tt++) {
                int jb = (lane + 32 * tt) << 3;
                #pragma unroll
                for (int e = 0; e < 4; e++) {
                    float lo, hi; up2(colAcc[tt * 4 + e], lo, hi);
                    *(float2*)(dst + jb + 2 * e) = make_float2(lo, hi);
                }
            }
        }
        __syncthreads();

        #pragma unroll
        for (int half = 0; half < 2; half++) {
            int j = tid + half * TPB;
            float sum = 0.0f;
            #pragma unroll
            for (int ww = 0; ww < 16; ww++) sum += shCol[ww * COLSTRIDE + j];
            g_colPart[pb][bid * NN + j] = sum;
        }
        if (tid == 0) {
            float e = 0.f;
            #pragma unroll
            for (int i = 0; i < 16; i++) e += shRed[i];
            g_errPart[pb][bid] = e;
        }
        grid_barrier(target);

        for (int j = tid; j < 1024; j += TPB) {
            const float* cp = g_colPart[pb] + (size_t)(tb * 8) * NN + j;
            float s0 = cp[0 * NN] + cp[1 * NN];
            float s1 = cp[2 * NN] + cp[3 * NN];
            float s2 = cp[4 * NN] + cp[5 * NN];
            float s3 = cp[6 * NN] + cp[7 * NN];
            float colSum = (s0 + s1) + (s2 + s3);
            float vo  = shV[j];
            float bo  = shB[j];
            float lse = __logf(fmaf(bo, colSum, 1e-6f));
            float vn  = EPSF * (log_mu - lse) + vo;
            shV[j] = vn;
            shB[j] = __expf(vn * inv_eps);
        }

        float ev = (tid < GRD) ? g_errPart[pb][tid] : 0.0f;
        ev = warp_sum(ev);
        if (lane == 0) shRed[w] = ev;
        __syncthreads();
        float err = (shRed[0] + shRed[1] + shRed[2] + shRed[3]) * (1.0f / BB);
        stop = (err < THRF);
        __syncthreads();
    }

    // ===== final: W = (K .* b) @ [y | 1 | y2]  ->  cost via exact C split ====
    {
        __half*  shP  = (__half*)shCol;             // 128 x 136 halves
        __half*  shY  = shP + 128 * 136;            // 128 x 72 halves
        float*   Wsm  = (float*)shCol;              // 128 x 80 floats (reuse)
        __half2* shBh = (__half2*)shV;              // b in fp16 pairs

        for (int i = tid; i < 512; i += TPB)
            shBh[i] = __floats2half2_rn(shB[2 * i], shB[2 * i + 1]);
        __syncthreads();

        float acc[9][4];
        #pragma unroll
        for (int nt = 0; nt < 9; nt++)
            #pragma unroll
            for (int e = 0; e < 4; e++) acc[nt][e] = 0.0f;

        const int it8 = w & 7;                      // i-tile (16 rows)
        const int jh  = w >> 3;                     // j half (64 j's)
        const unsigned pBase = (unsigned)__cvta_generic_to_shared(shP);
        const unsigned yBase = (unsigned)__cvta_generic_to_shared(shY);
        const int aRowOff = (lane & 7) + (lane & 8);
        const int aColOff = (lane & 16) >> 1;
        const int bRow = lane & 15;
        const int bCol = (lane >> 4) << 3;
        const int prow = tid >> 2, psub = tid & 3;

        for (int jt = 0; jt < 8; jt++) {
            const int j0t = jt * 128;
            // build P = K .* b  (fp16)
            {
                const uint4* Kr = (const uint4*)(g_Kh +
                    (size_t)(bid * 128 + prow) * NN + j0t + psub * 32);
                #pragma unroll
                for (int k = 0; k < 4; k++) {
                    uint4 kq = Kr[k];
                    __half2* kp = (__half2*)&kq;
                    #pragma unroll
                    for (int e = 0; e < 4; e++)
                        kp[e] = __hmul2(kp[e],
                                shBh[((j0t + psub * 32) >> 1) + k * 4 + e]);
                    *(uint4*)(shP + prow * 136 + psub * 32 + k * 8) = kq;
                }
                // build Y' = [y(fp16) | 1 | y2 | 0pad]
                const uint4* Yr = (const uint4*)(g_yf +
                    (size_t)(tb * NN + j0t + prow) * DD + psub * 16);
                *(uint4*)(shY + prow * 72 + psub * 16)     = Yr[0];
                *(uint4*)(shY + prow * 72 + psub * 16 + 8) = Yr[1];
                if (psub == 3) {
                    float y2v = g_y2[tb * NN + j0t + prow];
                    *(__half2*)(shY + prow * 72 + 64) = __floats2half2_rn(1.0f, y2v);
                    *(unsigned*)(shY + prow * 72 + 66) = 0u;
                    *(unsigned*)(shY + prow * 72 + 68) = 0u;
                    *(unsigned*)(shY + prow * 72 + 70) = 0u;
                }
            }
            __syncthreads();
            // mma: warp covers 16 i-rows x 72 d, over its 64-j half
            #pragma unroll
            for (int ks = 0; ks < 4; ks++) {
                const int jcol = jh * 64 + ks * 16;
                unsigned af[4];
                ldsm4(af[0], af[1], af[2], af[3],
                      pBase + ((it8 * 16 + aRowOff) * 136 + jcol + aColOff) * 2);
                const int jrow = jh * 64 + ks * 16 + bRow;
                #pragma unroll
                for (int nt = 0; nt < 4; nt++) {
                    unsigned b0, b1, b2, b3;
                    ldsm4t(b0, b1, b2, b3,
                           yBase + (jrow * 72 + nt * 16 + bCol) * 2);
                    mma16816h(acc[2 * nt],     af, b0, b1);
                    mma16816h(acc[2 * nt + 1], af, b2, b3);
                }
                unsigned c0, c1;
                ldsm2t(c0, c1, yBase + (jrow * 72 + 64) * 2);
                mma16816h(acc[8], af, c0, c1);
            }
            __syncthreads();
        }

        // combine j-halves into Wsm (fp32, stride 80)
        const int fr = it8 * 16 + (lane >> 2);
        const int fc = (lane & 3) * 2;
        if (jh == 1) {
            #pragma unroll
            for (int nt = 0; nt < 9; nt++) {
                *(float2*)(Wsm + fr * 80 + nt * 8 + fc) =
                    make_float2(acc[nt][0], acc[nt][1]);
                *(float2*)(Wsm + (fr + 8) * 80 + nt * 8 + fc) =
                    make_float2(acc[nt][2], acc[nt][3]);
            }
        }
        __syncthreads();
        if (jh == 0) {
            #pragma unroll
            for (int nt = 0; nt < 9; nt++) {
                float2 p0 = *(float2*)(Wsm + fr * 80 + nt * 8 + fc);
                float2 p1 = *(float2*)(Wsm + (fr + 8) * 80 + nt * 8 + fc);
                p0.x += acc[nt][0]; p0.y += acc[nt][1];
                p1.x += acc[nt][2]; p1.y += acc[nt][3];
                *(float2*)(Wsm + fr * 80 + nt * 8 + fc) = p0;
                *(float2*)(Wsm + (fr + 8) * 80 + nt * 8 + fc) = p1;
            }
        }
        __syncthreads();

        // extraction: cost_i = a_i (x2_i*W[64] + W[65] - 2 sum_d x_d W_d)
        float partial = 0.0f;
        {
            const int row = tid >> 2, sub = tid & 3;
            const float* Wr = Wsm + row * 80 + sub * 16;
            const uint4* xh4 = (const uint4*)(g_xh +
                (size_t)(bid * 128 + row) * DD + sub * 16);
            const uint4* xl4 = (const uint4*)(g_xl +
                (size_t)(bid * 128 + row) * DD + sub * 16);
            #pragma unroll
            for (int c = 0; c < 2; c++) {
                uint4 hq = xh4[c], lq = xl4[c];
                const __nv_bfloat162* hp = (const __nv_bfloat162*)&hq;
                const __nv_bfloat162* lp = (const __nv_bfloat162*)&lq;
                #pragma unroll
                for (int e = 0; e < 4; e++) {
                    float2 xh2 = __bfloat1622float2(hp[e]);
                    float2 xl2 = __bfloat1622float2(lp[e]);
                    partial += (xh2.x + xl2.x) * Wr[c * 8 + 2 * e];
                    partial += (xh2.y + xl2.y) * Wr[c * 8 + 2 * e + 1];
                }
            }
            partial *= -2.0f;
            partial += __shfl_xor_sync(0xffffffffu, partial, 1);
            partial += __shfl_xor_sync(0xffffffffu, partial, 2);
            if (sub == 0) {
                float tI = Wsm[row * 80 + 64];
                float mI = Wsm[row * 80 + 65];
                float x2i = g_x2[bid * 128 + row];
                float ai  = __expf(shU[row] * inv_eps);
                partial = ai * (x2i * tI + mI + partial);
            } else {
                partial = 0.0f;
            }
        }
        partial = warp_sum(partial);
        if (lane == 0) shRed[w] = partial;
        __syncthreads();
        if (tid == 0) {
            float e = 0.f;
            #pragma unroll
            for (int i = 0; i < 16; i++) e += shRed[i];
            atomicAdd(&g_cost, (double)e);
        }
        grid_barrier(target);
        if (bid == 0 && tid == 0) out[0] = (float)(g_cost * (1.0 / BB));
    }
}

// ---------------- launch ----------------
extern "C" void kernel_launch(void* const* d_in, const int* in_sizes, int n_in,
                              void* d_out, int out_size) {
    const float* x = (const float*)d_in[0];
    const float* y = (const float*)d_in[1];
    float* out = (float*)d_out;

    static int attrDone = 0;
    if (!attrDone) {
        cudaFuncSetAttribute(gemm_kernel,
                             cudaFuncAttributeMaxDynamicSharedMemorySize,
                             4 * TILEH * sizeof(__half));
        cudaFuncSetAttribute(sinkhorn_kernel,
                             cudaFuncAttributeMaxDynamicSharedMemorySize,
                             SH_FLOATS * sizeof(float));
        attrDone = 1;
    }

    softmax_kernel<<<(BB * NN * 8) / 256, 256>>>(x, y);
    gemm_kernel<<<dim3(8, 8, BB), 256, 4 * TILEH * sizeof(__half)>>>();
    sinkhorn_kernel<<<GRD, TPB, SH_FLOATS * sizeof(float)>>>(out);
}

// round 10
// speedup vs baseline: 1.1417x; 1.1417x over previous
#include <cuda_runtime.h>
#include <cuda_fp16.h>
#include <cuda_bf16.h>
#include <math.h>

// ---------------- problem constants ----------------
#define BB    16
#define NN    1024
#define DD    64
#define EPSF  0.1f
#define MAXIT 100
#define THRF  0.1f
#define GRD   128
#define TPB   512

// ---------------- packed f32x2 helpers ----------------
typedef unsigned long long ull;
__device__ __forceinline__ ull pk2(float lo, float hi) {
    ull r; asm("mov.b64 %0, {%1, %2};" : "=l"(r) : "f"(lo), "f"(hi)); return r;
}
__device__ __forceinline__ void up2(ull v, float& lo, float& hi) {
    asm("mov.b64 {%0, %1}, %2;" : "=f"(lo), "=f"(hi) : "l"(v));
}
#define FMA2(d, a, b) asm("fma.rn.f32x2 %0, %1, %2, %0;" : "+l"(d) : "l"(a), "l"(b))
#define MUL2(d, a, b) asm("mul.rn.f32x2 %0, %1, %2;" : "=l"(d) : "l"(a), "l"(b))

// butterfly-shuffle reductions
__device__ __forceinline__ float warp_sum(float v) {
    #pragma unroll
    for (int o = 16; o; o >>= 1) v += __shfl_xor_sync(0xffffffffu, v, o);
    return v;
}
__device__ __forceinline__ float seg8_sum(float v) {
    v += __shfl_xor_sync(0xffffffffu, v, 1);
    v += __shfl_xor_sync(0xffffffffu, v, 2);
    v += __shfl_xor_sync(0xffffffffu, v, 4);
    return v;
}

// ---------------- mma / ldmatrix helpers ----------------
__device__ __forceinline__ void ldsm4(unsigned& r0, unsigned& r1, unsigned& r2,
                                      unsigned& r3, unsigned addr) {
    asm volatile("ldmatrix.sync.aligned.m8n8.x4.shared.b16 {%0,%1,%2,%3}, [%4];"
                 : "=r"(r0), "=r"(r1), "=r"(r2), "=r"(r3) : "r"(addr));
}
__device__ __forceinline__ void mma16816(float* d, const unsigned* a,
                                         unsigned b0, unsigned b1) {
    asm volatile(
        "mma.sync.aligned.m16n8k16.row.col.f32.bf16.bf16.f32 "
        "{%0,%1,%2,%3}, {%4,%5,%6,%7}, {%8,%9}, {%0,%1,%2,%3};"
        : "+f"(d[0]), "+f"(d[1]), "+f"(d[2]), "+f"(d[3])
        : "r"(a[0]), "r"(a[1]), "r"(a[2]), "r"(a[3]), "r"(b0), "r"(b1));
}

// ---------------- device scratch ----------------
__device__ __nv_bfloat16 g_xh[BB * NN * DD];
__device__ __nv_bfloat16 g_xl[BB * NN * DD];
__device__ __nv_bfloat16 g_yh[BB * NN * DD];
__device__ __nv_bfloat16 g_yl[BB * NN * DD];
__device__ float g_x2[BB * NN];
__device__ float g_y2[BB * NN];
__device__ __align__(16) __half g_Ch[(size_t)BB * NN * NN]; // 32 MB fp16 cost
__device__ __align__(16) __half g_Kh[(size_t)BB * NN * NN]; // 32 MB fp16 kernel
__device__ float g_colPart[2][GRD * NN];
__device__ float g_errPart[2][GRD];
__device__ double g_cost;
__device__ unsigned g_bar;

// ---------------- softmax: 8 threads/row, no-max, seg8 shuffles -------------
__global__ void __launch_bounds__(256) softmax_kernel(const float* __restrict__ x,
                                                      const float* __restrict__ y) {
    if (blockIdx.x == 0 && threadIdx.x == 0) { g_cost = 0.0; g_bar = 0u; }
    int t  = blockIdx.x * blockDim.x + threadIdx.x;
    int g  = t >> 3;               // row id over both tensors
    int lg = t & 7;
    const float* src; __nv_bfloat16 *dh, *dl; float* nrm; int row;
    if (g < BB * NN) { row = g;           src = x; dh = g_xh; dl = g_xl; nrm = g_x2; }
    else             { row = g - BB * NN; src = y; dh = g_yh; dl = g_yl; nrm = g_y2; }

    const float4* r = (const float4*)(src + (size_t)row * DD);
    float4 v0 = r[lg * 2], v1 = r[lg * 2 + 1];
    float e[8] = {__expf(v0.x), __expf(v0.y), __expf(v0.z), __expf(v0.w),
                  __expf(v1.x), __expf(v1.y), __expf(v1.z), __expf(v1.w)};
    float s = ((e[0] + e[1]) + (e[2] + e[3])) + ((e[4] + e[5]) + (e[6] + e[7]));
    s = seg8_sum(s);
    float inv = 1.0f / s;

    float p[8]; float q = 0.0f;
    #pragma unroll
    for (int k = 0; k < 8; k++) { p[k] = e[k] * inv; q += p[k] * p[k]; }

    union { __nv_bfloat162 h2[4]; uint4 u; } hh, ll;
    #pragma unroll
    for (int k = 0; k < 4; k++) {
        __nv_bfloat16 h0 = __float2bfloat16_rn(p[2 * k]);
        __nv_bfloat16 h1 = __float2bfloat16_rn(p[2 * k + 1]);
        hh.h2[k].x = h0; hh.h2[k].y = h1;
        ll.h2[k].x = __float2bfloat16_rn(p[2 * k]     - __bfloat162float(h0));
        ll.h2[k].y = __float2bfloat16_rn(p[2 * k + 1] - __bfloat162float(h1));
    }
    *(uint4*)(dh + (size_t)row * DD + lg * 8) = hh.u;
    *(uint4*)(dl + (size_t)row * DD + lg * 8) = ll.u;

    q = seg8_sum(q);
    if (lg == 0) nrm[row] = q;
}

// ---------------- tensor GEMM: C = x2+y2-2XY^T (fp16), K = exp(-C/eps) -----
#define ROWP 72
#define TILEH (128 * ROWP)          // halves per tile
#define EPIST 136                   // epilogue smem stride (conflict-free)
__global__ void __launch_bounds__(256) gemm_kernel() {
    extern __shared__ __half sm[];  // compute: [Ah|Al|Bh|Bl]; epilogue: [C|K]
    const int b  = blockIdx.z;
    const int i0 = blockIdx.y * 128;
    const int j0 = blockIdx.x * 128;
    const int t  = threadIdx.x;
    const int wid  = t >> 5;
    const int lane = t & 31;
    const int wm = wid & 3;
    const int wn = wid >> 2;

    {
        const __nv_bfloat16* srcs[4] = {
            g_xh + ((size_t)b * NN + i0) * DD, g_xl + ((size_t)b * NN + i0) * DD,
            g_yh + ((size_t)b * NN + j0) * DD, g_yl + ((size_t)b * NN + j0) * DD };
        #pragma unroll
        for (int ts = 0; ts < 4; ts++) {
            const uint4* s = (const uint4*)srcs[ts];
            #pragma unroll
            for (int q = 0; q < 4; q++) {
                int idx = t + q * 256;
                int row = idx >> 3, seg = idx & 7;
                uint4 v = s[idx];
                *(uint4*)(sm + ts * TILEH + row * ROWP + seg * 8) = v;
            }
        }
    }
    __syncthreads();

    float acc[2][8][4];
    #pragma unroll
    for (int mt = 0; mt < 2; mt++)
        #pragma unroll
        for (int nt = 0; nt < 8; nt++)
            #pragma unroll
            for (int e = 0; e < 4; e++) acc[mt][nt][e] = 0.0f;

    const unsigned smBase = (unsigned)__cvta_generic_to_shared(sm);
    const int aRowOff = (lane & 7) + (lane & 8);
    const int aColOff = (lane & 16) >> 1;
    const int bRowOff = (lane & 7) + ((lane & 16) >> 1);
    const int bColOff = (lane & 8);

    #pragma unroll
    for (int pass = 0; pass < 3; pass++) {
        const int asel = (pass == 2) ? 1 : 0;
        const int bsel = (pass == 1) ? 1 : 0;
        const unsigned aBase = smBase + asel * TILEH * 2;
        const unsigned bBase = smBase + (2 + bsel) * TILEH * 2;
        #pragma unroll
        for (int ks = 0; ks < 4; ks++) {
            const int kcol = ks * 16;
            unsigned afr[2][4];
            #pragma unroll
            for (int mt = 0; mt < 2; mt++) {
                unsigned addr = aBase +
                    ((wm * 32 + mt * 16 + aRowOff) * ROWP + kcol + aColOff) * 2;
                ldsm4(afr[mt][0], afr[mt][1], afr[mt][2], afr[mt][3], addr);
            }
            unsigned bfr[4][4];
            #pragma unroll
            for (int nq = 0; nq < 4; nq++) {
                unsigned addr = bBase +
                    ((wn * 64 + nq * 16 + bRowOff) * ROWP + kcol + bColOff) * 2;
                ldsm4(bfr[nq][0], bfr[nq][1], bfr[nq][2], bfr[nq][3], addr);
            }
            #pragma unroll
            for (int mt = 0; mt < 2; mt++)
                #pragma unroll
                for (int nq = 0; nq < 4; nq++) {
                    mma16816(acc[mt][2 * nq],     afr[mt], bfr[nq][0], bfr[nq][1]);
                    mma16816(acc[mt][2 * nq + 1], afr[mt], bfr[nq][2], bfr[nq][3]);
                }
        }
    }

    // ---- epilogue: stage C/K through smem, coalesced 128B stores ----
    const int g  = lane >> 2;
    const int t4 = lane & 3;
    float y2v[16];
    #pragma unroll
    for (int nt = 0; nt < 8; nt++) {
        int gj = j0 + wn * 64 + nt * 8 + t4 * 2;
        y2v[2 * nt]     = g_y2[b * NN + gj];
        y2v[2 * nt + 1] = g_y2[b * NN + gj + 1];
    }
    __syncthreads();                       // tiles no longer needed
    __half* smC = sm;
    __half* smK = sm + 128 * EPIST;
    #pragma unroll
    for (int mt = 0; mt < 2; mt++) {
        #pragma unroll
        for (int hh = 0; hh < 2; hh++) {
            int lrow = wm * 32 + mt * 16 + hh * 8 + g;
            float x2i = g_x2[b * NN + i0 + lrow];
            #pragma unroll
            for (int nt = 0; nt < 8; nt++) {
                int lcol = wn * 64 + nt * 8 + t4 * 2;
                float d0 = acc[mt][nt][hh * 2 + 0];
                float d1 = acc[mt][nt][hh * 2 + 1];
                float c0 = x2i + y2v[2 * nt]     - 2.0f * d0;
                float c1 = x2i + y2v[2 * nt + 1] - 2.0f * d1;
                *(__half2*)(smC + lrow * EPIST + lcol) = __floats2half2_rn(c0, c1);
                *(__half2*)(smK + lrow * EPIST + lcol) =
                    __floats2half2_rn(__expf(-10.0f * c0), __expf(-10.0f * c1));
            }
        }
    }
    __syncthreads();
    {
        const __half* sarr[2] = {smC, smK};
        __half* darr[2] = {g_Ch, g_Kh};
        #pragma unroll
        for (int a = 0; a < 2; a++) {
            #pragma unroll
            for (int q = 0; q < 8; q++) {
                int idx = q * 256 + t;          // 0..2047
                int row = idx >> 4, seg = idx & 15;
                uint4 v = *(const uint4*)(sarr[a] + row * EPIST + seg * 8);
                *(uint4*)(darr[a] + ((size_t)b * NN + i0 + row) * NN + j0 + seg * 8) = v;
            }
        }
    }
}

// ---------------- software grid barrier (nanosleep backoff) ----------------
__device__ __forceinline__ void grid_barrier(unsigned& target) {
    target += GRD;
    __syncthreads();
    if (threadIdx.x == 0) {
        __threadfence();
        atomicAdd(&g_bar, 1u);
        volatile unsigned* p = &g_bar;
        while (*p < target) { __nanosleep(32); }
        __threadfence();
    }
    __syncthreads();
}

// ---------------- persistent Sinkhorn: 1 barrier / iter ----------------------
#define COLSTRIDE 1026
#define SH_FLOATS (1024 + 1024 + 128 + 16 * COLSTRIDE + 32)

__global__ void __launch_bounds__(TPB) sinkhorn_kernel(float* __restrict__ out) {
    extern __shared__ float sh[];
    float* shB   = sh;                  // exp(v/eps)
    float* shV   = sh + 1024;           // v
    float* shU   = sh + 2048;           // u (owned 128 rows)
    float* shCol = sh + 2176;
    float* shRed = shCol + 16 * COLSTRIDE;

    const int tid  = threadIdx.x;
    const int w    = tid >> 5;
    const int lane = tid & 31;
    const int bid  = blockIdx.x;
    const int tb   = bid >> 3;
    unsigned target = 0;
    const float log_mu  = logf(1.0f / NN + 1e-8f);
    const float inv_eps = 1.0f / EPSF;
    bool stop = false;

    for (int i = tid; i < 1024; i += TPB) { shB[i] = 1.0f; shV[i] = 0.0f; }
    if (tid < 128) shU[tid] = 0.0f;
    __syncthreads();

    for (int it = 0; it < MAXIT && !stop; ++it) {
        const int pb = it & 1;

        // hoist b into registers: lane's 32-j slice, reused across all 8 rows
        ull bReg[16];
        #pragma unroll
        for (int tt = 0; tt < 4; tt++) {
            const ull* bp = (const ull*)(shB + ((lane + 32 * tt) << 3));
            #pragma unroll
            for (int e = 0; e < 4; e++) bReg[tt * 4 + e] = bp[e];
        }

        ull colAcc[16];
        #pragma unroll
        for (int q = 0; q < 16; q++) colAcc[q] = 0ULL;
        float errAcc = 0.0f;
        const int rowLocalBase = w * 8;

        #pragma unroll 2
        for (int r = 0; r < 8; r++) {
            const int rl  = rowLocalBase + r;
            const int row = bid * 128 + rl;
            const uint4* __restrict__ Kr = (const uint4*)(g_Kh + (size_t)row * NN);

            // pass 1: row dot with b (K not cached in regs)
            uint4 q4[4];
            #pragma unroll
            for (int tt = 0; tt < 4; tt++) q4[tt] = Kr[lane + 32 * tt];
            ull s2 = 0ULL;
            #pragma unroll
            for (int tt = 0; tt < 4; tt++) {
                const __half2* hp = (const __half2*)&q4[tt];
                #pragma unroll
                for (int e = 0; e < 4; e++) {
                    float2 f = __half22float2(hp[e]);
                    FMA2(s2, pk2(f.x, f.y), bReg[tt * 4 + e]);
                }
            }
            float sx, sy; up2(s2, sx, sy);
            float s = warp_sum(sx + sy);

            float uo  = shU[rl];
            float ao  = __expf(uo * inv_eps);
            float lse = __logf(fmaf(ao, s, 1e-6f));
            float un  = EPSF * (log_mu - lse) + uo;
            float an  = __expf(un * inv_eps);
            if (lane == 0) { shU[rl] = un; errAcc += fabsf(un - uo); }
            ull ap = pk2(an, an);

            // pass 2: column accumulate (K reloaded, L1-hot)
            #pragma unroll
            for (int tt = 0; tt < 4; tt++) q4[tt] = Kr[lane + 32 * tt];
            #pragma unroll
            for (int tt = 0; tt < 4; tt++) {
                const __half2* hp = (const __half2*)&q4[tt];
                #pragma unroll
                for (int e = 0; e < 4; e++) {
                    float2 f = __half22float2(hp[e]);
                    FMA2(colAcc[tt * 4 + e], ap, pk2(f.x, f.y));
                }
            }
        }

        if (lane == 0) shRed[w] = errAcc;
        {
            float* dst = shCol + w * COLSTRIDE;
            #pragma unroll
            for (int tt = 0; tt < 4; tt++) {
                int jb = (lane + 32 * tt) << 3;
                #pragma unroll
                for (int e = 0; e < 4; e++) {
                    float lo, hi; up2(colAcc[tt * 4 + e], lo, hi);
                    *(float2*)(dst + jb + 2 * e) = make_float2(lo, hi);
                }
            }
        }
        __syncthreads();

        #pragma unroll
        for (int half = 0; half < 2; half++) {
            int j = tid + half * TPB;
            float sum = 0.0f;
            #pragma unroll
            for (int ww = 0; ww < 16; ww++) sum += shCol[ww * COLSTRIDE + j];
            g_colPart[pb][bid * NN + j] = sum;
        }
        if (tid == 0) {
            float e = 0.f;
            #pragma unroll
            for (int i = 0; i < 16; i++) e += shRed[i];
            g_errPart[pb][bid] = e;
        }
        grid_barrier(target);

        for (int j = tid; j < 1024; j += TPB) {
            const float* cp = g_colPart[pb] + (size_t)(tb * 8) * NN + j;
            float s0 = cp[0 * NN] + cp[1 * NN];
            float s1 = cp[2 * NN] + cp[3 * NN];
            float s2 = cp[4 * NN] + cp[5 * NN];
            float s3 = cp[6 * NN] + cp[7 * NN];
            float colSum = (s0 + s1) + (s2 + s3);
            float vo  = shV[j];
            float bo  = shB[j];
            float lse = __logf(fmaf(bo, colSum, 1e-6f));
            float vn  = EPSF * (log_mu - lse) + vo;
            shV[j] = vn;
            shB[j] = __expf(vn * inv_eps);
        }

        float ev = (tid < GRD) ? g_errPart[pb][tid] : 0.0f;
        ev = warp_sum(ev);
        if (lane == 0) shRed[w] = ev;
        __syncthreads();
        float err = (shRed[0] + shRed[1] + shRed[2] + shRed[3]) * (1.0f / BB);
        stop = (err < THRF);
        __syncthreads();
    }

    // ===== final: cost = sum_ij a_i * K_ij * b_j * C_ij (b in registers) ====
    {
        ull bReg[16];
        #pragma unroll
        for (int tt = 0; tt < 4; tt++) {
            const ull* bp = (const ull*)(shB + ((lane + 32 * tt) << 3));
            #pragma unroll
            for (int e = 0; e < 4; e++) bReg[tt * 4 + e] = bp[e];
        }
        float acc = 0.0f;
        const int rowLocalBase = w * 8;
        #pragma unroll 2
        for (int r = 0; r < 8; r++) {
            const int rl  = rowLocalBase + r;
            const int row = bid * 128 + rl;
            const uint4* __restrict__ Kr = (const uint4*)(g_Kh + (size_t)row * NN);
            const uint4* __restrict__ Cr = (const uint4*)(g_Ch + (size_t)row * NN);
            ull s2 = 0ULL;
            #pragma unroll
            for (int tt = 0; tt < 4; tt++) {
                uint4 kq = Kr[lane + 32 * tt];
                uint4 cq = Cr[lane + 32 * tt];
                const __half2* kp = (const __half2*)&kq;
                const __half2* cp = (const __half2*)&cq;
                #pragma unroll
                for (int e = 0; e < 4; e++) {
                    float2 kf = __half22float2(kp[e]);
                    float2 cf = __half22float2(cp[e]);
                    ull kb;
                    MUL2(kb, pk2(kf.x, kf.y), bReg[tt * 4 + e]);
                    FMA2(s2, kb, pk2(cf.x, cf.y));
                }
            }
            float sx, sy; up2(s2, sx, sy);
            float s = warp_sum(sx + sy);
            if (lane == 0) acc += __expf(shU[rl] * inv_eps) * s;
        }
        if (lane == 0) shRed[w] = acc;
        __syncthreads();
        if (tid == 0) {
            float e = 0.f;
            #pragma unroll
            for (int i = 0; i < 16; i++) e += shRed[i];
            atomicAdd(&g_cost, (double)e);
        }
        grid_barrier(target);
        if (bid == 0 && tid == 0) out[0] = (float)(g_cost * (1.0 / BB));
    }
}

// ---------------- launch ----------------
extern "C" void kernel_launch(void* const* d_in, const int* in_sizes, int n_in,
                              void* d_out, int out_size) {
    const float* x = (const float*)d_in[0];
    const float* y = (const float*)d_in[1];
    float* out = (float*)d_out;

    static int attrDone = 0;
    if (!attrDone) {
        cudaFuncSetAttribute(gemm_kernel,
                             cudaFuncAttributeMaxDynamicSharedMemorySize,
                             4 * TILEH * sizeof(__half));
        cudaFuncSetAttribute(sinkhorn_kernel,
                             cudaFuncAttributeMaxDynamicSharedMemorySize,
                             SH_FLOATS * sizeof(float));
        attrDone = 1;
    }

    softmax_kernel<<<(2 * BB * NN * 8) / 256, 256>>>(x, y);
    gemm_kernel<<<dim3(8, 8, BB), 256, 4 * TILEH * sizeof(__half)>>>();
    sinkhorn_kernel<<<GRD, TPB, SH_FLOATS * sizeof(float)>>>(out);
}